// round 9
// baseline (speedup 1.0000x reference)
#include <cuda_runtime.h>
#include <cuda_bf16.h>
#include <math.h>
#include <stdint.h>

#define B_  8
#define T_  12
#define N_  1024
#define C_  64
#define D_  10
#define BT_ (B_*T_)   // 96

// ======================= mma.sync / ldmatrix helpers ========================
__device__ __forceinline__ uint32_t sm_addr(const void* p) {
    return (uint32_t)__cvta_generic_to_shared(p);
}
__device__ __forceinline__ void ldsm_x4(unsigned* r, uint32_t a) {
    asm volatile("ldmatrix.sync.aligned.m8n8.x4.shared.b16 {%0,%1,%2,%3}, [%4];"
                 : "=r"(r[0]), "=r"(r[1]), "=r"(r[2]), "=r"(r[3]) : "r"(a));
}
__device__ __forceinline__ void ldsm_x4t(unsigned* r, uint32_t a) {
    asm volatile("ldmatrix.sync.aligned.m8n8.x4.trans.shared.b16 {%0,%1,%2,%3}, [%4];"
                 : "=r"(r[0]), "=r"(r[1]), "=r"(r[2]), "=r"(r[3]) : "r"(a));
}
__device__ __forceinline__ void mma16816(float* d, const unsigned* a, const unsigned* b) {
    asm volatile("mma.sync.aligned.m16n8k16.row.col.f32.bf16.bf16.f32 "
                 "{%0,%1,%2,%3}, {%4,%5,%6,%7}, {%8,%9}, {%0,%1,%2,%3};"
                 : "+f"(d[0]), "+f"(d[1]), "+f"(d[2]), "+f"(d[3])
                 : "r"(a[0]), "r"(a[1]), "r"(a[2]), "r"(a[3]),
                   "r"(b[0]), "r"(b[1]));
}
__device__ __forceinline__ void split_bf16(float v, __nv_bfloat16& h, __nv_bfloat16& l) {
    h = __float2bfloat16(v);
    l = __float2bfloat16(v - __bfloat162float(h));
}
__device__ __forceinline__ unsigned pack2(__nv_bfloat16 lo, __nv_bfloat16 hi) {
    __nv_bfloat162 v = __halves2bfloat162(lo, hi);
    return *reinterpret_cast<unsigned*>(&v);
}

// stage rows x (COLS8*8) bf16 tile gmem->smem (padded pitch, 16B vectors)
template<int COLS8>
__device__ __forceinline__ void stage(__nv_bfloat16* s, int pitch,
                                      const __nv_bfloat16* __restrict__ g,
                                      size_t gstride, int rows) {
    int tot = rows * COLS8;
    for (int i = threadIdx.x; i < tot; i += blockDim.x) {
        int r = i / COLS8, c = (i % COLS8) * 8;
        *(uint4*)(s + r*pitch + c) = *(const uint4*)(g + (size_t)r*gstride + c);
    }
}

// warp-level split-bf16 MMA over one 64-K chunk (MI m-tiles x 32 n)
template<int MI>
__device__ __forceinline__ void warp_mma(float (&acc)[MI][4][4],
        const __nv_bfloat16* Ah, const __nv_bfloat16* Al, int pa,
        const __nv_bfloat16* Bh, const __nv_bfloat16* Bl, int pb,
        int m_base, int n_base, int lane) {
    const int ar = lane & 15, ac = (lane >> 4) * 8;
#pragma unroll
    for (int ks = 0; ks < 4; ks++) {
        unsigned ah[MI][4], al[MI][4], bh[2][4], bl[2][4];
#pragma unroll
        for (int mi = 0; mi < MI; mi++) {
            int off = (m_base + mi*16 + ar)*pa + ks*16 + ac;
            ldsm_x4(ah[mi], sm_addr(Ah + off));
            ldsm_x4(al[mi], sm_addr(Al + off));
        }
#pragma unroll
        for (int njp = 0; njp < 2; njp++) {
            int off = (ks*16 + ar)*pb + n_base + njp*16 + ac;
            ldsm_x4t(bh[njp], sm_addr(Bh + off));
            ldsm_x4t(bl[njp], sm_addr(Bl + off));
        }
#pragma unroll
        for (int mi = 0; mi < MI; mi++)
#pragma unroll
            for (int j = 0; j < 4; j++) {
                const unsigned* ph = &bh[j>>1][(j&1)*2];
                const unsigned* pl = &bl[j>>1][(j&1)*2];
                mma16816(acc[mi][j], ah[mi], ph);
                mma16816(acc[mi][j], ah[mi], pl);
                mma16816(acc[mi][j], al[mi], ph);
            }
    }
}

// ======================= scratch globals ====================================
__device__ float         g_supports[N_*N_];
__device__ __nv_bfloat16 g_sup_hi[N_*N_], g_sup_lo[N_*N_];
__device__ __nv_bfloat16 g_A_hi[N_*N_],   g_A_lo[N_*N_];
__device__ __nv_bfloat16 g_x_hi[(size_t)BT_*N_*C_],  g_x_lo[(size_t)BT_*N_*C_];
__device__ __nv_bfloat16 g_xT_hi[(size_t)BT_*C_*N_], g_xT_lo[(size_t)BT_*C_*N_];
__device__ __nv_bfloat16 g_wp_hi[(size_t)1024*4096], g_wp_lo[(size_t)1024*4096];
__device__ float         g_weights[N_*C_*C_];
__device__ float         g_bias[N_*C_];
__device__ float         g_bias_part[8*N_*C_];
__device__ float         g_M[(size_t)B_*N_*N_];      // 32 MB
__device__ float         g_invS[(size_t)B_*N_*N_];   // 32 MB
__device__ float         g_xg[(size_t)BT_*N_*C_];

// ======================= small kernels ======================================
__global__ void k_supports(const float* __restrict__ e1,
                           const float* __restrict__ e2) {
    int j = blockIdx.x * 16 + threadIdx.x;
    int i = blockIdx.y * 16 + threadIdx.y;
    float d = 0.f;
#pragma unroll
    for (int k = 0; k < D_; k++)
        d += e1[i*D_+k]*e2[j*D_+k] - e2[i*D_+k]*e1[j*D_+k];
    float v = fmaxf(tanhf(d), 0.f);
    if (i == j) v += 1.f;
    g_supports[i*N_ + j] = v;
    __nv_bfloat16 h, l; split_bf16(v, h, l);
    g_sup_hi[i*N_ + j] = h; g_sup_lo[i*N_ + j] = l;
}

__global__ void k_softmaxA(const float* __restrict__ A_sym) {
    int row = blockIdx.x, t = threadIdx.x;
    const float* r = A_sym + (size_t)row * N_;
    __shared__ float red[256];
    float vals[4]; float m = -3.4e38f;
#pragma unroll
    for (int q = 0; q < 4; q++) { vals[q] = r[t + q*256]; m = fmaxf(m, vals[q]); }
    red[t] = m; __syncthreads();
    for (int s = 128; s > 0; s >>= 1) { if (t < s) red[t] = fmaxf(red[t], red[t+s]); __syncthreads(); }
    m = red[0]; __syncthreads();
    float sum = 0.f;
#pragma unroll
    for (int q = 0; q < 4; q++) { vals[q] = expf(vals[q] - m); sum += vals[q]; }
    red[t] = sum; __syncthreads();
    for (int s = 128; s > 0; s >>= 1) { if (t < s) red[t] += red[t+s]; __syncthreads(); }
    float inv = 1.f / red[0];
#pragma unroll
    for (int q = 0; q < 4; q++) {
        float v = vals[q] * inv;
        __nv_bfloat16 h, l; split_bf16(v, h, l);
        size_t idx = (size_t)row*N_ + t + q*256;
        g_A_hi[idx] = h; g_A_lo[idx] = l;
    }
}

__global__ void k_cvt_x(const float* __restrict__ x) {
    int bt = blockIdx.y, n0 = blockIdx.x * 64;
    __shared__ float tbuf[64][65];
    int tid = threadIdx.x;
    for (int e = tid; e < 4096; e += 256) {
        int n = e >> 6, c = e & 63;
        float v = x[((size_t)bt*N_ + n0 + n)*C_ + c];
        tbuf[n][c] = v;
        __nv_bfloat16 h, l; split_bf16(v, h, l);
        size_t idx = ((size_t)bt*N_ + n0 + n)*C_ + c;
        g_x_hi[idx] = h; g_x_lo[idx] = l;
    }
    __syncthreads();
    for (int e = tid; e < 4096; e += 256) {
        int c = e >> 6, n = e & 63;
        float v = tbuf[n][c];
        __nv_bfloat16 h, l; split_bf16(v, h, l);
        size_t idx = ((size_t)bt*C_ + c)*N_ + n0 + n;
        g_xT_hi[idx] = h; g_xT_lo[idx] = l;
    }
}

__global__ void k_cvt_wp(const float* __restrict__ wp) {
    size_t i = ((size_t)blockIdx.x*256 + threadIdx.x)*4;
    float4 v = *(const float4*)(wp + i);
    __nv_bfloat16 h, l;
    split_bf16(v.x, h, l); g_wp_hi[i+0] = h; g_wp_lo[i+0] = l;
    split_bf16(v.y, h, l); g_wp_hi[i+1] = h; g_wp_lo[i+1] = l;
    split_bf16(v.z, h, l); g_wp_hi[i+2] = h; g_wp_lo[i+2] = l;
    split_bf16(v.w, h, l); g_wp_hi[i+3] = h; g_wp_lo[i+3] = l;
}

// ======================= weights GEMM (unchanged from R8) ===================
#define OW_AH 0
#define OW_AL 9216
#define OW_BH 18432
#define OW_BL 27136
#define SMW_BYTES ((27136 + 8704) * 2)

__global__ void __launch_bounds__(256) k_weights_mma() {
    extern __shared__ __nv_bfloat16 sm[];
    const int n0 = blockIdx.y * 128, io0 = blockIdx.x * 128;
    const int tid = threadIdx.x, wid = tid >> 5, lane = tid & 31;
    const int m_base = (wid >> 2) * 64, n_base = (wid & 3) * 32;
    float acc[4][4][4] = {};
    for (int ch = 0; ch < 16; ch++) {
        int ko = ch * 64;
        stage<8> (sm+OW_AH,  72, g_sup_hi + (size_t)n0*N_ + ko, N_, 128);
        stage<8> (sm+OW_AL,  72, g_sup_lo + (size_t)n0*N_ + ko, N_, 128);
        stage<16>(sm+OW_BH, 136, g_wp_hi + (size_t)ko*4096 + io0, 4096, 64);
        stage<16>(sm+OW_BL, 136, g_wp_lo + (size_t)ko*4096 + io0, 4096, 64);
        __syncthreads();
        warp_mma<4>(acc, sm+OW_AH, sm+OW_AL, 72, sm+OW_BH, sm+OW_BL, 136,
                    m_base, n_base, lane);
        __syncthreads();
    }
#pragma unroll
    for (int mi = 0; mi < 4; mi++)
#pragma unroll
        for (int j = 0; j < 4; j++) {
            int r = n0 + m_base + mi*16 + (lane >> 2);
            int c = io0 + n_base + j*8 + (lane & 3)*2;
            g_weights[(size_t)r*4096 + c]       = acc[mi][j][0];
            g_weights[(size_t)r*4096 + c + 1]   = acc[mi][j][1];
            g_weights[(size_t)(r+8)*4096 + c]   = acc[mi][j][2];
            g_weights[(size_t)(r+8)*4096 + c+1] = acc[mi][j][3];
        }
}

// ======================= attention: stats pass ==============================
// block tile: 128 n-rows x 64 m-cols, 8 warps (warp 32x32), loop t = 0..11.
// Writes M = max_t score, invS = 1/sum_t exp(score - M).
#define ST_XNH 0
#define ST_XNL 9216
#define ST_MTH 18432
#define ST_MTL 23040
#define SMST_BYTES (27648 * 2)   // 55296

__global__ void __launch_bounds__(256) k_stats() {
    extern __shared__ __nv_bfloat16 sm[];
    const int b = blockIdx.z, n0 = blockIdx.y * 128, m0 = blockIdx.x * 64;
    const int tid = threadIdx.x, wid = tid >> 5, lane = tid & 31;
    const int rb = (wid >> 1) * 32, cb = (wid & 1) * 32;
    float mr[2][4][4], sr[2][4][4];
#pragma unroll
    for (int mi = 0; mi < 2; mi++)
#pragma unroll
        for (int j = 0; j < 4; j++)
#pragma unroll
            for (int q = 0; q < 4; q++) { mr[mi][j][q] = -3.4e38f; sr[mi][j][q] = 0.f; }

    for (int t = 0; t < T_; t++) {
        int bt = b*T_ + t;
        __syncthreads();
        stage<8>(sm+ST_XNH, 72, g_x_hi + ((size_t)bt*N_ + n0)*C_, C_, 128);
        stage<8>(sm+ST_XNL, 72, g_x_lo + ((size_t)bt*N_ + n0)*C_, C_, 128);
        stage<8>(sm+ST_MTH, 72, g_xT_hi + (size_t)bt*C_*N_ + m0, N_, 64);
        stage<8>(sm+ST_MTL, 72, g_xT_lo + (size_t)bt*C_*N_ + m0, N_, 64);
        __syncthreads();
        float acc[2][4][4] = {};
        warp_mma<2>(acc, sm+ST_XNH, sm+ST_XNL, 72, sm+ST_MTH, sm+ST_MTL, 72,
                    rb, cb, lane);
#pragma unroll
        for (int mi = 0; mi < 2; mi++)
#pragma unroll
            for (int j = 0; j < 4; j++)
#pragma unroll
                for (int q = 0; q < 4; q++) {
                    float a = acc[mi][j][q];
                    float mn = fmaxf(mr[mi][j][q], a);
                    sr[mi][j][q] = sr[mi][j][q]*__expf(mr[mi][j][q]-mn) + __expf(a-mn);
                    mr[mi][j][q] = mn;
                }
    }
#pragma unroll
    for (int mi = 0; mi < 2; mi++)
#pragma unroll
        for (int j = 0; j < 4; j++)
#pragma unroll
            for (int q = 0; q < 4; q++) {
                int r = n0 + rb + mi*16 + (lane >> 2) + ((q >= 2) ? 8 : 0);
                int c = m0 + cb + j*8 + (lane & 3)*2 + (q & 1);
                size_t idx = ((size_t)b*N_ + r)*N_ + c;
                g_M[idx]    = mr[mi][j][q];
                g_invS[idx] = 1.f / sr[mi][j][q];
            }
}

// ======================= attention: fused sa pass ===========================
// block: (b,t, 128 n-rows). 8 warps, each owns 16 n-rows x full m-chunk.
// Streams 16 m-chunks: recompute score (bit-identical to k_stats order),
// P = exp(s-M)*invS, repack C-frags -> A-frags, PV MMA into out accs.
#define FB_XNH 0
#define FB_XNL 9216
#define FB_MTH 18432
#define FB_MTL 23040
#define FB_PVH 27648
#define FB_PVL 32256
#define SMFB_BYTES (36864 * 2)   // 73728

__global__ void __launch_bounds__(256) k_sa_fused(const float* __restrict__ beta,
                                                  float* __restrict__ out) {
    extern __shared__ __nv_bfloat16 sm[];
    const int bt = blockIdx.y, b = bt / T_;
    const int n0 = blockIdx.x * 128;
    const int tid = threadIdx.x, wid = tid >> 5, lane = tid & 31;
    const int ar = lane & 15, ac = (lane >> 4) * 8;
    const int rq = lane >> 2, cp = (lane & 3) * 2;

    stage<8>(sm+FB_XNH, 72, g_x_hi + ((size_t)bt*N_ + n0)*C_, C_, 128);
    stage<8>(sm+FB_XNL, 72, g_x_lo + ((size_t)bt*N_ + n0)*C_, C_, 128);

    float oacc[8][4] = {};
    const float* Mb = g_M    + (size_t)b*N_*N_;
    const float* Ib = g_invS + (size_t)b*N_*N_;
    const int gr = n0 + wid*16 + rq;

    for (int mc = 0; mc < 16; mc++) {
        const int m0 = mc * 64;
        __syncthreads();
        stage<8>(sm+FB_MTH, 72, g_xT_hi + (size_t)bt*C_*N_ + m0, N_, 64);
        stage<8>(sm+FB_MTL, 72, g_xT_lo + (size_t)bt*C_*N_ + m0, N_, 64);
        stage<8>(sm+FB_PVH, 72, g_x_hi + ((size_t)bt*N_ + m0)*C_, C_, 64);
        stage<8>(sm+FB_PVL, 72, g_x_lo + ((size_t)bt*N_ + m0)*C_, C_, 64);
        __syncthreads();

        // ---- score tile: 16 n-rows (this warp) x 64 m-cols ----
        float sacc[8][4] = {};
#pragma unroll
        for (int ks = 0; ks < 4; ks++) {
            unsigned ah[4], al[4];
            ldsm_x4(ah, sm_addr(sm+FB_XNH + (wid*16 + ar)*72 + ks*16 + ac));
            ldsm_x4(al, sm_addr(sm+FB_XNL + (wid*16 + ar)*72 + ks*16 + ac));
#pragma unroll
            for (int jp = 0; jp < 4; jp++) {
                unsigned bh[4], bl[4];
                ldsm_x4t(bh, sm_addr(sm+FB_MTH + (ks*16 + ar)*72 + jp*16 + ac));
                ldsm_x4t(bl, sm_addr(sm+FB_MTL + (ks*16 + ar)*72 + jp*16 + ac));
                mma16816(sacc[2*jp],   ah, bh);   mma16816(sacc[2*jp],   ah, bl);
                mma16816(sacc[2*jp],   al, bh);
                mma16816(sacc[2*jp+1], ah, bh+2); mma16816(sacc[2*jp+1], ah, bl+2);
                mma16816(sacc[2*jp+1], al, bh+2);
            }
        }

        // ---- P = exp(s - M) * invS, repack into A-frags, PV MMA ----
#pragma unroll
        for (int kg = 0; kg < 4; kg++) {
            unsigned ph[4], pl[4];
#pragma unroll
            for (int jj = 0; jj < 2; jj++) {
                int j = 2*kg + jj;
                int gc = m0 + j*8 + cp;
                float2 M0 = *(const float2*)(Mb + (size_t)gr*N_ + gc);
                float2 I0 = *(const float2*)(Ib + (size_t)gr*N_ + gc);
                float2 M8 = *(const float2*)(Mb + (size_t)(gr+8)*N_ + gc);
                float2 I8 = *(const float2*)(Ib + (size_t)(gr+8)*N_ + gc);
                float p0 = __expf(sacc[j][0] - M0.x) * I0.x;
                float p1 = __expf(sacc[j][1] - M0.y) * I0.y;
                float p2 = __expf(sacc[j][2] - M8.x) * I8.x;
                float p3 = __expf(sacc[j][3] - M8.y) * I8.y;
                __nv_bfloat16 h0, l0, h1, l1, h2, l2, h3, l3;
                split_bf16(p0, h0, l0); split_bf16(p1, h1, l1);
                split_bf16(p2, h2, l2); split_bf16(p3, h3, l3);
                ph[jj*2+0] = pack2(h0, h1);  ph[jj*2+1] = pack2(h2, h3);
                pl[jj*2+0] = pack2(l0, l1);  pl[jj*2+1] = pack2(l2, l3);
            }
#pragma unroll
            for (int cj = 0; cj < 4; cj++) {
                unsigned bh[4], bl[4];
                ldsm_x4t(bh, sm_addr(sm+FB_PVH + (kg*16 + ar)*72 + cj*16 + ac));
                ldsm_x4t(bl, sm_addr(sm+FB_PVL + (kg*16 + ar)*72 + cj*16 + ac));
                mma16816(oacc[2*cj],   ph, bh);   mma16816(oacc[2*cj],   ph, bl);
                mma16816(oacc[2*cj],   pl, bh);
                mma16816(oacc[2*cj+1], ph, bh+2); mma16816(oacc[2*cj+1], ph, bl+2);
                mma16816(oacc[2*cj+1], pl, bh+2);
            }
        }
    }

    const float be = beta[0];
#pragma unroll
    for (int j = 0; j < 8; j++) {
        int c = j*8 + cp;
        size_t i0 = ((size_t)bt*N_ + gr)*C_ + c;
        size_t i8 = ((size_t)bt*N_ + gr + 8)*C_ + c;
        out[i0]   += be * fmaxf(oacc[j][0], 0.f);
        out[i0+1] += be * fmaxf(oacc[j][1], 0.f);
        out[i8]   += be * fmaxf(oacc[j][2], 0.f);
        out[i8+1] += be * fmaxf(oacc[j][3], 0.f);
    }
}

// ======================= dual GEMM (unchanged from R8) ======================
#define OD_A1H 0
#define OD_A1L 9216
#define OD_A2H 18432
#define OD_A2L 27648
#define OD_BH  36864
#define OD_BL  41472
#define SMD_BYTES ((41472 + 4608) * 2)

__global__ void __launch_bounds__(256) k_dual_mma(const float* __restrict__ gamma,
                                                  float* __restrict__ out) {
    extern __shared__ __nv_bfloat16 sm[];
    const int bt = blockIdx.y, r0 = blockIdx.x * 128;
    const int tid = threadIdx.x, wid = tid >> 5, lane = tid & 31;
    const int m_base = (wid >> 1) * 32, n_base = (wid & 1) * 32;
    float acc1[2][4][4] = {}, acc2[2][4][4] = {};
    for (int ch = 0; ch < 16; ch++) {
        int ko = ch * 64;
        stage<8>(sm+OD_A1H, 72, g_A_hi   + (size_t)(r0)*N_ + ko, N_, 128);
        stage<8>(sm+OD_A1L, 72, g_A_lo   + (size_t)(r0)*N_ + ko, N_, 128);
        stage<8>(sm+OD_A2H, 72, g_sup_hi + (size_t)(r0)*N_ + ko, N_, 128);
        stage<8>(sm+OD_A2L, 72, g_sup_lo + (size_t)(r0)*N_ + ko, N_, 128);
        stage<8>(sm+OD_BH,  72, g_x_hi + ((size_t)bt*N_ + ko)*C_, C_, 64);
        stage<8>(sm+OD_BL,  72, g_x_lo + ((size_t)bt*N_ + ko)*C_, C_, 64);
        __syncthreads();
        warp_mma<2>(acc1, sm+OD_A1H, sm+OD_A1L, 72, sm+OD_BH, sm+OD_BL, 72,
                    m_base, n_base, lane);
        warp_mma<2>(acc2, sm+OD_A2H, sm+OD_A2L, 72, sm+OD_BH, sm+OD_BL, 72,
                    m_base, n_base, lane);
        __syncthreads();
    }
    const float g = gamma[0];
#pragma unroll
    for (int mi = 0; mi < 2; mi++)
#pragma unroll
        for (int j = 0; j < 4; j++) {
            int r = r0 + m_base + mi*16 + (lane >> 2);
            int c = n_base + j*8 + (lane & 3)*2;
            size_t i0 = ((size_t)bt*N_ + r)*C_ + c;
            size_t i8 = ((size_t)bt*N_ + r + 8)*C_ + c;
            out[i0]   = g * fmaxf(acc1[mi][j][0], 0.f);
            out[i0+1] = g * fmaxf(acc1[mi][j][1], 0.f);
            out[i8]   = g * fmaxf(acc1[mi][j][2], 0.f);
            out[i8+1] = g * fmaxf(acc1[mi][j][3], 0.f);
            g_xg[i0]   = acc2[mi][j][0];
            g_xg[i0+1] = acc2[mi][j][1];
            g_xg[i8]   = acc2[mi][j][2];
            g_xg[i8+1] = acc2[mi][j][3];
        }
}

// ======================= bias (fp32, split-K) ===============================
__global__ void k_bias_part(const float* __restrict__ bp) {
    __shared__ float As[16][68];
    __shared__ float Bs[16][68];
    int tid = threadIdx.x, tx = tid & 15, ty = tid >> 4;
    int m0 = blockIdx.x * 64, kb = blockIdx.y * 128;
    float acc[4][4] = {};
    for (int k0 = kb; k0 < kb + 128; k0 += 16) {
#pragma unroll
        for (int e = tid; e < 1024; e += 256) {
            int mm = e >> 4, kk = e & 15;
            As[kk][mm] = g_supports[(size_t)(m0+mm)*N_ + k0 + kk];
        }
#pragma unroll
        for (int e = tid; e < 1024; e += 256) {
            int kk = e >> 6, nn = e & 63;
            Bs[kk][nn] = bp[(size_t)(k0+kk)*C_ + nn];
        }
        __syncthreads();
#pragma unroll
        for (int k = 0; k < 16; k++) {
            float4 ra = *(const float4*)&As[k][ty<<2];
            float4 rb = *(const float4*)&Bs[k][tx<<2];
            float a[4] = {ra.x, ra.y, ra.z, ra.w};
            float b[4] = {rb.x, rb.y, rb.z, rb.w};
#pragma unroll
            for (int i = 0; i < 4; i++)
#pragma unroll
                for (int j = 0; j < 4; j++) acc[i][j] += a[i]*b[j];
        }
        __syncthreads();
    }
    float* dst = g_bias_part + (size_t)blockIdx.y * N_ * C_;
#pragma unroll
    for (int i = 0; i < 4; i++)
#pragma unroll
        for (int j = 0; j < 4; j++)
            dst[(size_t)(m0+(ty<<2)+i)*C_ + (tx<<2) + j] = acc[i][j];
}
__global__ void k_bias_red() {
    int i = blockIdx.x * 256 + threadIdx.x;
    float s = 0.f;
#pragma unroll
    for (int c = 0; c < 8; c++) s += g_bias_part[(size_t)c*N_*C_ + i];
    g_bias[i] = s;
}

// ---------------- gconv: out += alpha*relu(xg[:,n,:] @ W[n] + bias[n]) ------
__global__ void k_gconv(const float* __restrict__ alpha,
                        float* __restrict__ out) {
    int n = blockIdx.x, tid = threadIdx.x;
    __shared__ float Ws[64*64];
    __shared__ float Xs[96][64];
    __shared__ float bs[64];
#pragma unroll
    for (int e = tid; e < 4096; e += 256) Ws[e] = g_weights[(size_t)n*4096 + e];
    if (tid < 64) bs[tid] = g_bias[(size_t)n*64 + tid];
#pragma unroll
    for (int e = tid; e < 96*64; e += 256) {
        int r = e >> 6, c = e & 63;
        Xs[r][c] = g_xg[((size_t)r*N_ + n)*C_ + c];
    }
    __syncthreads();
    float al = alpha[0];
    int o = tid & 63, rg = tid >> 6;
    for (int r = rg; r < 96; r += 4) {
        float acc = bs[o];
#pragma unroll
        for (int i = 0; i < 64; i++) acc = fmaf(Xs[r][i], Ws[i*64 + o], acc);
        size_t idx = ((size_t)r*N_ + n)*C_ + o;
        out[idx] += al * fmaxf(acc, 0.f);
    }
}

// ======================= launch =============================================
extern "C" void kernel_launch(void* const* d_in, const int* in_sizes, int n_in,
                              void* d_out, int out_size) {
    (void)in_sizes; (void)n_in; (void)out_size;
    const float* x     = (const float*)d_in[0];
    const float* e1    = (const float*)d_in[1];
    const float* e2    = (const float*)d_in[2];
    const float* A_sym = (const float*)d_in[3];
    const float* wp    = (const float*)d_in[4];
    const float* bp    = (const float*)d_in[5];
    const float* alpha = (const float*)d_in[6];
    const float* beta  = (const float*)d_in[7];
    const float* gamma = (const float*)d_in[8];
    float* out = (float*)d_out;

    cudaFuncSetAttribute(k_weights_mma, cudaFuncAttributeMaxDynamicSharedMemorySize, SMW_BYTES);
    cudaFuncSetAttribute(k_stats,       cudaFuncAttributeMaxDynamicSharedMemorySize, SMST_BYTES);
    cudaFuncSetAttribute(k_sa_fused,    cudaFuncAttributeMaxDynamicSharedMemorySize, SMFB_BYTES);
    cudaFuncSetAttribute(k_dual_mma,    cudaFuncAttributeMaxDynamicSharedMemorySize, SMD_BYTES);

    k_supports   <<<dim3(N_/16, N_/16), dim3(16,16)>>>(e1, e2);
    k_softmaxA   <<<N_, 256>>>(A_sym);
    k_cvt_x      <<<dim3(N_/64, BT_), 256>>>(x);
    k_cvt_wp     <<<(1024*4096)/(256*4), 256>>>(wp);
    k_weights_mma<<<dim3(32, 8), 256, SMW_BYTES>>>();
    k_bias_part  <<<dim3(N_/64, 8), 256>>>(bp);
    k_bias_red   <<<(N_*C_)/256, 256>>>();
    k_dual_mma   <<<dim3(8, BT_), 256, SMD_BYTES>>>(gamma, out);
    k_stats      <<<dim3(16, 8, B_), 256, SMST_BYTES>>>();
    k_sa_fused   <<<dim3(8, BT_), 256, SMFB_BYTES>>>(beta, out);
    k_gconv      <<<N_, 256>>>(alpha, out);
}